// round 2
// baseline (speedup 1.0000x reference)
#include <cuda_runtime.h>
#include <math.h>
#include <float.h>

#define N      8192
#define C0     64
#define E      128
#define EXT    132          // 128 embedding + 3 xyz + 1 bias/norm term
#define KSEL   16
#define NSLICES 16
#define SLICE  (N / NSLICES)   // 512
#define TJ     8
#define DROWS  128

// ---------------- scratch (__device__ globals; no allocation allowed) ----------------
// combos: 0 = t11(feat1) [dir0 side1], 1 = t22(feat2) [dir0 side2],
//         2 = t11(feat2) [dir1 side1], 3 = t22(feat1) [dir1 side2]
__device__ float g_f[4][N][C0];        // projected features, row-major [n][c]
__device__ float g_gt[4][EXT][N];      // normalized ext embeddings, transposed [k][n]
__device__ float g_psc[2][N][NSLICES * KSEL];  // partial top-k scores
__device__ int   g_pix[2][N][NSLICES * KSEL];  // partial top-k indices

__device__ __forceinline__ float leaky(float x) { return fmaxf(x, 0.1f * x); }

// =====================================================================================
// Kernel P: feature projection + dist embedding + normalize + extended rows
// grid (N/32, 4 combos), 256 threads, dynamic smem 66816B
// =====================================================================================
__global__ __launch_bounds__(256) void kp(
    const float* __restrict__ pc1, const float* __restrict__ pc2,
    const float* __restrict__ feat1, const float* __restrict__ feat2,
    const float* __restrict__ t11w, const float* __restrict__ t11b,
    const float* __restrict__ t22w, const float* __restrict__ t22b,
    const float* __restrict__ dw, const float* __restrict__ db)
{
    extern __shared__ float sm[];
    float* s_tw   = sm;                    // [64][65]
    float* s_dw   = sm + 4160;             // [128][65]
    float* s_feat = sm + 4160 + 8320;      // [64][33]
    float* s_f    = sm + 4160 + 8320 + 2112; // [32][65]
    float* s_ss   = s_f + 2080;            // [32]

    const int combo = blockIdx.y;
    const float* feat = (combo == 0 || combo == 3) ? feat1 : feat2;
    const float* pc   = (combo == 0 || combo == 3) ? pc1   : pc2;
    const float* w    = (combo & 1) ? t22w : t11w;
    const float* b    = (combo & 1) ? t22b : t11b;
    const int side2   = combo & 1;

    const int tid = threadIdx.x;
    const int n0  = blockIdx.x * 32;

    for (int i = tid; i < 4096; i += 256) s_tw[(i >> 6) * 65 + (i & 63)] = w[i];
    for (int i = tid; i < 8192; i += 256) s_dw[(i >> 6) * 65 + (i & 63)] = dw[i];
    for (int i = tid; i < 64 * 32; i += 256) {
        int c = i >> 5, np = i & 31;
        s_feat[c * 33 + np] = feat[c * N + n0 + np];
    }
    if (tid < 32) s_ss[tid] = 0.f;
    __syncthreads();

    // f = t_w @ feat + t_b  (each thread: 8 (n,o) outputs)
    for (int it = 0; it < 8; ++it) {
        int i = tid + it * 256;
        int o = i & 63, n = i >> 6;
        float acc = __ldg(b + o);
        #pragma unroll
        for (int c = 0; c < 64; ++c)
            acc = fmaf(s_tw[o * 65 + c], s_feat[c * 33 + n], acc);
        s_f[n * 65 + o] = acc;
        g_f[combo][n0 + n][o] = acc;
    }
    __syncthreads();

    // g = dist_w @ f + dist_b, then normalize
    const int n = tid & 31, eg = tid >> 5;
    float gv[16];
    float ss = 0.f;
    #pragma unroll 2
    for (int t = 0; t < 16; ++t) {
        int e = eg * 16 + t;
        float acc = __ldg(db + e);
        #pragma unroll
        for (int c = 0; c < 64; ++c)
            acc = fmaf(s_dw[e * 65 + c], s_f[n * 65 + c], acc);
        gv[t] = acc;
        ss = fmaf(acc, acc, ss);
    }
    atomicAdd(&s_ss[n], ss);
    __syncthreads();
    const float scale = 1.f / (sqrtf(s_ss[n]) + 1e-8f);
    #pragma unroll
    for (int t = 0; t < 16; ++t) {
        int e = eg * 16 + t;
        g_gt[combo][e][n0 + n] = gv[t] * scale;
    }

    // extended rows: side1 -> [2x, -1]; side2 -> [x, |x|^2]
    if (tid < 32) {
        int nn = n0 + tid;
        float x0 = pc[0 * N + nn], x1 = pc[1 * N + nn], x2 = pc[2 * N + nn];
        if (side2) {
            g_gt[combo][128][nn] = x0;
            g_gt[combo][129][nn] = x1;
            g_gt[combo][130][nn] = x2;
            g_gt[combo][131][nn] = x0 * x0 + x1 * x1 + x2 * x2;
        } else {
            g_gt[combo][128][nn] = 2.f * x0;
            g_gt[combo][129][nn] = 2.f * x1;
            g_gt[combo][130][nn] = 2.f * x2;
            g_gt[combo][131][nn] = -1.f;
        }
    }
}

// =====================================================================================
// Kernel D: 132-dim score "GEMM" + per-row streaming top-16 (partial, per slice)
// grid (N/128 rowtiles, NSLICES, 2 dirs), 128 threads (1 row per thread)
// dynamic smem: s_a [EXT][128] (per-thread row spill) + s_b [TJ][EXT]
// =====================================================================================
__global__ __launch_bounds__(128, 3) void kd()
{
    extern __shared__ float sh[];
    float* s_a = sh;                 // [EXT][128]
    float* s_b = sh + EXT * DROWS;   // [TJ][EXT]

    const int tid  = threadIdx.x;
    const int dir  = blockIdx.z;
    const int row0 = blockIdx.x * DROWS;
    const int j0   = blockIdx.y * SLICE;

    const float* __restrict__ g1 = &g_gt[dir * 2][0][0];
    const float* __restrict__ g2 = &g_gt[dir * 2 + 1][0][0];

    // each thread stages its own extended row into its shared column (no sync needed)
    #pragma unroll 4
    for (int k = 0; k < EXT; ++k)
        s_a[k * DROWS + tid] = g1[k * N + row0 + tid];

    float ts[KSEL];
    int   ti[KSEL];
    #pragma unroll
    for (int q = 0; q < KSEL; ++q) { ts[q] = -FLT_MAX; ti[q] = 0; }

    for (int jt = 0; jt < SLICE; jt += TJ) {
        __syncthreads();
        for (int i = tid; i < TJ * EXT; i += 128) {
            int jj = i & (TJ - 1), k = i >> 3;
            s_b[jj * EXT + k] = g2[k * N + j0 + jt + jj];
        }
        __syncthreads();

        float acc[TJ];
        #pragma unroll
        for (int jj = 0; jj < TJ; ++jj) acc[jj] = 0.f;

        #pragma unroll 3
        for (int kc = 0; kc < EXT; kc += 4) {
            float a0 = s_a[(kc + 0) * DROWS + tid];
            float a1 = s_a[(kc + 1) * DROWS + tid];
            float a2 = s_a[(kc + 2) * DROWS + tid];
            float a3 = s_a[(kc + 3) * DROWS + tid];
            #pragma unroll
            for (int jj = 0; jj < TJ; ++jj) {
                float4 bv = *reinterpret_cast<const float4*>(&s_b[jj * EXT + kc]);
                acc[jj] = fmaf(a3, bv.w, fmaf(a2, bv.z, fmaf(a1, bv.y, fmaf(a0, bv.x, acc[jj]))));
            }
        }

        // batched top-16 insertion: bitmask of passers, drained warp-cooperatively
        unsigned m = 0;
        #pragma unroll
        for (int jj = 0; jj < TJ; ++jj)
            if (acc[jj] > ts[KSEL - 1]) m |= (1u << jj);

        while (__any_sync(0xffffffffu, m != 0)) {
            if (m) {
                int jj = __ffs(m) - 1;
                m &= m - 1;
                float cs = acc[jj];
                if (cs > ts[KSEL - 1]) {
                    int ci = j0 + jt + jj;
                    #pragma unroll
                    for (int q = 0; q < KSEL; ++q) {
                        if (cs > ts[q]) {
                            float tf = ts[q]; ts[q] = cs; cs = tf;
                            int   tx = ti[q]; ti[q] = ci; ci = tx;
                        }
                    }
                }
            }
        }
    }

    const int row = row0 + tid;
    const int sl  = blockIdx.y;
    #pragma unroll
    for (int q = 0; q < KSEL; ++q) {
        g_psc[dir][row][sl * KSEL + q] = ts[q];
        g_pix[dir][row][sl * KSEL + q] = ti[q];
    }
}

// =====================================================================================
// Kernel M: merge 256 partials -> exact top-16 (warp argmax on packed u64 keys),
// then gather + pos-conv + add + leaky + MLP + leaky + maxpool over K
// grid (N/8, 2 dirs), 256 threads (1 warp per row)
// =====================================================================================
__device__ __forceinline__ unsigned long long makeKey(float s, int j)
{
    unsigned u = __float_as_uint(s);
    u = (u & 0x80000000u) ? ~u : (u | 0x80000000u);   // monotone float->uint
    return ((unsigned long long)u << 32) | (unsigned)(~j); // tie -> smaller j wins
}

__global__ __launch_bounds__(256) void km(
    const float* __restrict__ pc1, const float* __restrict__ pc2,
    const float* __restrict__ posw, const float* __restrict__ posb,
    const float* __restrict__ mw, const float* __restrict__ mb,
    float* __restrict__ out)
{
    __shared__ float s_mw[64 * 65];
    __shared__ int   s_sel[8][KSEL];
    __shared__ float s_v[8][65];

    const int tid  = threadIdx.x;
    const int lane = tid & 31;
    const int rg   = tid >> 5;          // row-group (warp) 0..7
    const int dir  = blockIdx.y;
    const int row  = blockIdx.x * 8 + rg;

    const float* x1p = dir ? pc2 : pc1;
    const float* x2p = dir ? pc1 : pc2;
    const float* q1  = &g_f[dir * 2][0][0];
    const float* q2  = &g_f[dir * 2 + 1][0][0];

    for (int i = tid; i < 4096; i += 256)
        s_mw[(i >> 6) * 65 + (i & 63)] = mw[i];

    // --- build keys: lane owns elems lane + 32*t ---
    unsigned long long k[8];
    #pragma unroll
    for (int t = 0; t < 8; ++t) {
        int e = lane + 32 * t;
        k[t] = makeKey(g_psc[dir][row][e], g_pix[dir][row][e]);
    }

    // --- 16 rounds of warp argmax ---
    #pragma unroll 1
    for (int r = 0; r < KSEL; ++r) {
        unsigned long long m = k[0];
        #pragma unroll
        for (int t = 1; t < 8; ++t) m = (k[t] > m) ? k[t] : m;
        #pragma unroll
        for (int off = 16; off; off >>= 1) {
            unsigned long long o = __shfl_xor_sync(0xffffffffu, m, off);
            m = (o > m) ? o : m;
        }
        if (lane == 0) s_sel[rg][r] = (int)(~(unsigned)m);
        #pragma unroll
        for (int t = 0; t < 8; ++t)
            if (k[t] == m) k[t] = 0ULL;   // keys unique per row -> single owner
    }
    __syncthreads();   // covers s_mw and s_sel

    // --- gather + MLP; lane handles channels (lane, lane+32) ---
    const float x10 = x1p[row], x11 = x1p[N + row], x12 = x1p[2 * N + row];
    const float q1a = q1[row * 64 + lane];
    const float q1b = q1[row * 64 + lane + 32];
    const float pa0 = __ldg(posw + lane * 3 + 0), pa1 = __ldg(posw + lane * 3 + 1), pa2 = __ldg(posw + lane * 3 + 2);
    const float pb0 = __ldg(posw + (lane + 32) * 3 + 0), pb1 = __ldg(posw + (lane + 32) * 3 + 1), pb2 = __ldg(posw + (lane + 32) * 3 + 2);
    const float ba  = __ldg(posb + lane),      bb  = __ldg(posb + lane + 32);
    const float mba = __ldg(mb + lane),        mbb = __ldg(mb + lane + 32);

    float bestA = -FLT_MAX, bestB = -FLT_MAX;

    #pragma unroll 1
    for (int kk = 0; kk < KSEL; ++kk) {
        int j = s_sel[rg][kk];
        float d0 = x2p[j] - x10, d1 = x2p[N + j] - x11, d2 = x2p[2 * N + j] - x12;
        float posA = fmaf(pa2, d2, fmaf(pa1, d1, fmaf(pa0, d0, ba)));
        float posB = fmaf(pb2, d2, fmaf(pb1, d1, fmaf(pb0, d0, bb)));
        float va = leaky(q2[j * 64 + lane]      + q1a + posA);
        float vb = leaky(q2[j * 64 + lane + 32] + q1b + posB);
        s_v[rg][lane]      = va;
        s_v[rg][lane + 32] = vb;
        __syncwarp();
        float ha = mba, hb = mbb;
        #pragma unroll
        for (int c = 0; c < 64; ++c) {
            float vc = s_v[rg][c];
            ha = fmaf(s_mw[lane * 65 + c],        vc, ha);
            hb = fmaf(s_mw[(lane + 32) * 65 + c], vc, hb);
        }
        bestA = fmaxf(bestA, leaky(ha));
        bestB = fmaxf(bestB, leaky(hb));
        __syncwarp();
    }

    out[dir * (64 * N) + lane * N + row]        = bestA;
    out[dir * (64 * N) + (lane + 32) * N + row] = bestB;
}

// =====================================================================================
extern "C" void kernel_launch(void* const* d_in, const int* in_sizes, int n_in,
                              void* d_out, int out_size)
{
    const float* pc1   = (const float*)d_in[0];
    const float* pc2   = (const float*)d_in[1];
    const float* feat1 = (const float*)d_in[2];
    const float* feat2 = (const float*)d_in[3];
    const float* t11w  = (const float*)d_in[4];
    const float* t11b  = (const float*)d_in[5];
    const float* t22w  = (const float*)d_in[6];
    const float* t22b  = (const float*)d_in[7];
    const float* posw  = (const float*)d_in[8];
    const float* posb  = (const float*)d_in[9];
    const float* dw    = (const float*)d_in[10];
    const float* db    = (const float*)d_in[11];
    const float* mw    = (const float*)d_in[12];
    const float* mb    = (const float*)d_in[13];
    float* out = (float*)d_out;

    const int smP = 66816;
    const int smD = (EXT * DROWS + TJ * EXT) * (int)sizeof(float);  // 71808
    cudaFuncSetAttribute(kp, cudaFuncAttributeMaxDynamicSharedMemorySize, smP);
    cudaFuncSetAttribute(kd, cudaFuncAttributeMaxDynamicSharedMemorySize, smD);

    kp<<<dim3(N / 32, 4), 256, smP>>>(pc1, pc2, feat1, feat2,
                                      t11w, t11b, t22w, t22b, dw, db);
    kd<<<dim3(N / DROWS, NSLICES, 2), DROWS, smD>>>();
    km<<<dim3(N / 8, 2), 256>>>(pc1, pc2, posw, posb, mw, mb, out);
}

// round 4
// speedup vs baseline: 1.5545x; 1.5545x over previous
#include <cuda_runtime.h>
#include <math.h>
#include <float.h>
#include <stdint.h>

#define N      8192
#define C0     64
#define KSEL   16
#define TCAND  24
#define MT     128
#define NT     64
#define NTILE  (N / NT)        // 128
#define KEXT   136             // 128 emb + 3 xyz + 1 + 4 zero pad
#define ASTR   140             // smem row stride (floats) for A/B
#define CSTR   65

// ---------------- scratch ----------------
__device__ __align__(128) float g_f[4][N][C0];     // projected features [n][c]
__device__ __align__(128) float g_ge[4][N][KEXT];  // extended rows
__device__ int g_cand[2][N][TCAND];

__device__ __forceinline__ float leaky(float x) { return fmaxf(x, 0.1f * x); }

__device__ __forceinline__ uint32_t smem_u32(const void* p) {
    uint32_t a;
    asm("{ .reg .u64 t; cvta.to.shared.u64 t, %1; cvt.u32.u64 %0, t; }" : "=r"(a) : "l"(p));
    return a;
}
__device__ __forceinline__ void cp16(uint32_t dst, const void* src) {
    asm volatile("cp.async.cg.shared.global [%0], [%1], 16;" :: "r"(dst), "l"(src));
}
#define CP_COMMIT() asm volatile("cp.async.commit_group;" ::: "memory")
#define CP_WAIT0()  asm volatile("cp.async.wait_group 0;" ::: "memory")

__device__ __forceinline__ void mma_tf32(float* c, uint32_t a0, uint32_t a1,
                                         uint32_t a2, uint32_t a3,
                                         uint32_t b0, uint32_t b1) {
    asm volatile(
        "mma.sync.aligned.m16n8k8.row.col.f32.tf32.tf32.f32 "
        "{%0,%1,%2,%3}, {%4,%5,%6,%7}, {%8,%9}, {%0,%1,%2,%3};"
        : "+f"(c[0]), "+f"(c[1]), "+f"(c[2]), "+f"(c[3])
        : "r"(a0), "r"(a1), "r"(a2), "r"(a3), "r"(b0), "r"(b1));
}

// smem floats: A [128*140], B [2][64*140], C [128*65]
#define SM_A 0
#define SM_B (MT * ASTR)                    // 17920
#define SM_C (SM_B + 2 * NT * ASTR)         // 35840
#define SM_TOT_F (SM_C + MT * CSTR)         // 44160
#define SM_BYTES (SM_TOT_F * 4)             // 176640

// =====================================================================================
// Kernel P: projections + dist embedding + normalize + extended rows
// =====================================================================================
__global__ __launch_bounds__(256) void kp(
    const float* __restrict__ pc1, const float* __restrict__ pc2,
    const float* __restrict__ feat1, const float* __restrict__ feat2,
    const float* __restrict__ t11w, const float* __restrict__ t11b,
    const float* __restrict__ t22w, const float* __restrict__ t22b,
    const float* __restrict__ dw, const float* __restrict__ db)
{
    extern __shared__ float sm[];
    float* s_tw   = sm;
    float* s_dw   = sm + 4160;
    float* s_feat = sm + 4160 + 8320;
    float* s_f    = sm + 4160 + 8320 + 2112;
    float* s_ss   = s_f + 2080;

    const int combo = blockIdx.y;
    const float* feat = (combo == 0 || combo == 3) ? feat1 : feat2;
    const float* pc   = (combo == 0 || combo == 3) ? pc1   : pc2;
    const float* w    = (combo & 1) ? t22w : t11w;
    const float* b    = (combo & 1) ? t22b : t11b;
    const int side2   = combo & 1;

    const int tid = threadIdx.x;
    const int n0  = blockIdx.x * 32;

    for (int i = tid; i < 4096; i += 256) s_tw[(i >> 6) * 65 + (i & 63)] = w[i];
    for (int i = tid; i < 8192; i += 256) s_dw[(i >> 6) * 65 + (i & 63)] = dw[i];
    for (int i = tid; i < 64 * 32; i += 256) {
        int c = i >> 5, np = i & 31;
        s_feat[c * 33 + np] = feat[c * N + n0 + np];
    }
    if (tid < 32) s_ss[tid] = 0.f;
    __syncthreads();

    for (int it = 0; it < 8; ++it) {
        int i = tid + it * 256;
        int o = i & 63, n = i >> 6;
        float acc = __ldg(b + o);
        #pragma unroll
        for (int c = 0; c < 64; ++c)
            acc = fmaf(s_tw[o * 65 + c], s_feat[c * 33 + n], acc);
        s_f[n * 65 + o] = acc;
        g_f[combo][n0 + n][o] = acc;
    }
    __syncthreads();

    const int n = tid & 31, eg = tid >> 5;
    float gv[16];
    float ss = 0.f;
    #pragma unroll 2
    for (int t = 0; t < 16; ++t) {
        int e = eg * 16 + t;
        float acc = __ldg(db + e);
        #pragma unroll
        for (int c = 0; c < 64; ++c)
            acc = fmaf(s_dw[e * 65 + c], s_f[n * 65 + c], acc);
        gv[t] = acc;
        ss = fmaf(acc, acc, ss);
    }
    atomicAdd(&s_ss[n], ss);
    __syncthreads();
    const float scale = 1.f / (sqrtf(s_ss[n]) + 1e-8f);
    #pragma unroll
    for (int t = 0; t < 16; ++t)
        g_ge[combo][n0 + n][eg * 16 + t] = gv[t] * scale;

    if (tid < 32) {
        int nn = n0 + tid;
        float x0 = pc[0 * N + nn], x1 = pc[1 * N + nn], x2 = pc[2 * N + nn];
        float* row = &g_ge[combo][nn][128];
        if (side2) {
            row[0] = x0; row[1] = x1; row[2] = x2;
            row[3] = x0 * x0 + x1 * x1 + x2 * x2;
        } else {
            row[0] = 2.f * x0; row[1] = 2.f * x1; row[2] = 2.f * x2;
            row[3] = -1.f;
        }
        row[4] = 0.f; row[5] = 0.f; row[6] = 0.f; row[7] = 0.f;
    }
}

// =====================================================================================
// Kernel D: tf32 mma.sync score GEMM (M=128/CTA, full N sweep) + streaming top-24
// 128 threads (4 warps). A resident smem, B double-buffered cp.async, C staged smem.
// =====================================================================================
__global__ __launch_bounds__(128, 1) void kd()
{
    extern __shared__ float sh[];
    const uint32_t sb = smem_u32(sh);
    float* s_a = sh + SM_A;
    float* s_c = sh + SM_C;

    const int tid  = threadIdx.x;
    const int wid  = tid >> 5, lane = tid & 31;
    const int dir  = blockIdx.y;
    const int row0 = blockIdx.x * MT;

    const float* __restrict__ gA = &g_ge[dir * 2][0][0];
    const float* __restrict__ gB = &g_ge[dir * 2 + 1][0][0];

    // ---- A resident: 128 rows x 34 float4 ----
    for (int it = 0; it < 34; ++it) {
        int i = tid + it * 128;               // 0..4351
        int r = i / 34, q = i % 34;
        cp16(sb + (SM_A + r * ASTR + q * 4) * 4,
             gA + (size_t)(row0 + r) * KEXT + q * 4);
    }
    // ---- B tile 0 prefetch ----
    for (int it = 0; it < 17; ++it) {
        int i = tid + it * 128;               // 0..2175
        int r = i / 34, q = i % 34;
        cp16(sb + (SM_B + r * ASTR + q * 4) * 4,
             gB + (size_t)r * KEXT + q * 4);
    }
    CP_COMMIT();
    CP_WAIT0();
    __syncthreads();

    float ts[TCAND];
    int   ti[TCAND];
    #pragma unroll
    for (int q = 0; q < TCAND; ++q) { ts[q] = -FLT_MAX; ti[q] = 0; }

    const int r0 = wid * 32 + (lane >> 2);    // fragment base row
    const int kq = lane & 3;
    const int jq = lane >> 2;

    for (int t = 0; t < NTILE; ++t) {
        const float* s_b = sh + SM_B + (t & 1) * (NT * ASTR);

        // prefetch next tile into other buffer
        if (t + 1 < NTILE) {
            const uint32_t dstb = sb + (SM_B + ((t + 1) & 1) * (NT * ASTR)) * 4;
            const float* srcb = gB + (size_t)(t + 1) * NT * KEXT;
            for (int it = 0; it < 17; ++it) {
                int i = tid + it * 128;
                int r = i / 34, q = i % 34;
                cp16(dstb + (r * ASTR + q * 4) * 4, srcb + (size_t)r * KEXT + q * 4);
            }
            CP_COMMIT();
        }

        // ---- MMA: C[2][8][4] = A(32 rows) x B(64 cols), K=136 ----
        float c[2][8][4];
        #pragma unroll
        for (int rb = 0; rb < 2; ++rb)
            #pragma unroll
            for (int cb = 0; cb < 8; ++cb)
                #pragma unroll
                for (int q = 0; q < 4; ++q) c[rb][cb][q] = 0.f;

        #pragma unroll 1
        for (int kb = 0; kb < 17; ++kb) {
            const int kbase = kb * 8;
            uint32_t a[2][4];
            #pragma unroll
            for (int rb = 0; rb < 2; ++rb) {
                const float* ap = s_a + (r0 + rb * 16) * ASTR + kbase + kq;
                a[rb][0] = __float_as_uint(ap[0]);
                a[rb][1] = __float_as_uint(ap[8 * ASTR]);
                a[rb][2] = __float_as_uint(ap[4]);
                a[rb][3] = __float_as_uint(ap[8 * ASTR + 4]);
            }
            uint32_t b[8][2];
            #pragma unroll
            for (int cb = 0; cb < 8; ++cb) {
                const float* bp = s_b + (cb * 8 + jq) * ASTR + kbase + kq;
                b[cb][0] = __float_as_uint(bp[0]);
                b[cb][1] = __float_as_uint(bp[4]);
            }
            #pragma unroll
            for (int rb = 0; rb < 2; ++rb)
                #pragma unroll
                for (int cb = 0; cb < 8; ++cb)
                    mma_tf32(c[rb][cb], a[rb][0], a[rb][1], a[rb][2], a[rb][3],
                             b[cb][0], b[cb][1]);
        }
        __syncthreads();

        // ---- stage C to smem ----
        #pragma unroll
        for (int rb = 0; rb < 2; ++rb) {
            const int rr = r0 + rb * 16;
            #pragma unroll
            for (int cb = 0; cb < 8; ++cb) {
                const int cc = cb * 8 + (lane & 3) * 2;
                s_c[rr * CSTR + cc]           = c[rb][cb][0];
                s_c[rr * CSTR + cc + 1]       = c[rb][cb][1];
                s_c[(rr + 8) * CSTR + cc]     = c[rb][cb][2];
                s_c[(rr + 8) * CSTR + cc + 1] = c[rb][cb][3];
            }
        }
        __syncthreads();

        // ---- per-row (1 thread = 1 row) streaming top-24 ----
        const int jb0 = t * NT;
        const float* crow = s_c + tid * CSTR;
        #pragma unroll 1
        for (int cb = 0; cb < 8; ++cb) {
            float acc[8];
            unsigned m = 0;
            #pragma unroll
            for (int jj = 0; jj < 8; ++jj) {
                acc[jj] = crow[cb * 8 + jj];
                if (acc[jj] > ts[TCAND - 1]) m |= (1u << jj);
            }
            while (__any_sync(0xffffffffu, m != 0)) {
                if (m) {
                    int jj = __ffs(m) - 1;
                    m &= m - 1;
                    float cs = acc[jj];
                    if (cs > ts[TCAND - 1]) {
                        int ci = jb0 + cb * 8 + jj;
                        #pragma unroll
                        for (int q = 0; q < TCAND; ++q) {
                            if (cs > ts[q]) {
                                float tf = ts[q]; ts[q] = cs; cs = tf;
                                int   tx = ti[q]; ti[q] = ci; ci = tx;
                            }
                        }
                    }
                }
            }
        }
        CP_WAIT0();
        __syncthreads();
    }

    #pragma unroll
    for (int q = 0; q < TCAND; ++q)
        g_cand[dir][row0 + tid][q] = ti[q];
}

// =====================================================================================
// Kernel M: exact fp32 rescore of 24 candidates -> top-16 -> gather+MLP+maxpool
// =====================================================================================
__device__ __forceinline__ unsigned long long makeKey(float s, int j)
{
    unsigned u = __float_as_uint(s);
    u = (u & 0x80000000u) ? ~u : (u | 0x80000000u);
    return ((unsigned long long)u << 32) | (unsigned)(~j);
}

__global__ __launch_bounds__(256) void km(
    const float* __restrict__ pc1, const float* __restrict__ pc2,
    const float* __restrict__ posw, const float* __restrict__ posb,
    const float* __restrict__ mw, const float* __restrict__ mb,
    float* __restrict__ out)
{
    __shared__ float s_mw[64 * 65];
    __shared__ float s_g1[8][KEXT];
    __shared__ int   s_sel[8][KSEL];
    __shared__ float s_v[8][65];

    const int tid  = threadIdx.x;
    const int lane = tid & 31;
    const int rg   = tid >> 5;
    const int dir  = blockIdx.y;
    const int row  = blockIdx.x * 8 + rg;

    const float* x1p = dir ? pc2 : pc1;
    const float* x2p = dir ? pc1 : pc2;
    const float* q1  = &g_f[dir * 2][0][0];
    const float* q2  = &g_f[dir * 2 + 1][0][0];
    const float* g1  = &g_ge[dir * 2][0][0];
    const float* g2  = &g_ge[dir * 2 + 1][0][0];

    for (int i = tid; i < 4096; i += 256)
        s_mw[(i >> 6) * 65 + (i & 63)] = mw[i];
    for (int i = tid; i < 8 * KEXT; i += 256)
        s_g1[i / KEXT][i % KEXT] =
            g1[(size_t)(blockIdx.x * 8 + i / KEXT) * KEXT + (i % KEXT)];
    __syncthreads();

    // exact rescore (lane < 24); pad zeros [132..135] contribute 0
    unsigned long long key = 0ULL;
    if (lane < TCAND) {
        int j = g_cand[dir][row][lane];
        const float4* g2r = (const float4*)(g2 + (size_t)j * KEXT);
        float s = 0.f;
        #pragma unroll 8
        for (int kqq = 0; kqq < 34; ++kqq) {
            float4 av = *(const float4*)&s_g1[rg][kqq * 4];
            float4 bv = __ldg(g2r + kqq);
            s = fmaf(av.x, bv.x, s); s = fmaf(av.y, bv.y, s);
            s = fmaf(av.z, bv.z, s); s = fmaf(av.w, bv.w, s);
        }
        key = makeKey(s, j);
    }

    #pragma unroll 1
    for (int r = 0; r < KSEL; ++r) {
        unsigned long long mx = key;
        #pragma unroll
        for (int off = 16; off; off >>= 1) {
            unsigned long long o = __shfl_xor_sync(0xffffffffu, mx, off);
            mx = (o > mx) ? o : mx;
        }
        if (lane == 0) s_sel[rg][r] = (int)(~(unsigned)mx);
        if (key == mx) key = 0ULL;
    }
    __syncwarp();

    const float x10 = x1p[row], x11 = x1p[N + row], x12 = x1p[2 * N + row];
    const float q1a = q1[row * 64 + lane];
    const float q1b = q1[row * 64 + lane + 32];
    const float pa0 = __ldg(posw + lane * 3 + 0), pa1 = __ldg(posw + lane * 3 + 1), pa2 = __ldg(posw + lane * 3 + 2);
    const float pb0 = __ldg(posw + (lane + 32) * 3 + 0), pb1 = __ldg(posw + (lane + 32) * 3 + 1), pb2 = __ldg(posw + (lane + 32) * 3 + 2);
    const float ba  = __ldg(posb + lane),      bb  = __ldg(posb + lane + 32);
    const float mba = __ldg(mb + lane),        mbb = __ldg(mb + lane + 32);

    float bestA = -FLT_MAX, bestB = -FLT_MAX;

    #pragma unroll 1
    for (int kk = 0; kk < KSEL; ++kk) {
        int j = s_sel[rg][kk];
        float d0 = x2p[j] - x10, d1 = x2p[N + j] - x11, d2 = x2p[2 * N + j] - x12;
        float posA = fmaf(pa2, d2, fmaf(pa1, d1, fmaf(pa0, d0, ba)));
        float posB = fmaf(pb2, d2, fmaf(pb1, d1, fmaf(pb0, d0, bb)));
        float va = leaky(q2[j * 64 + lane]      + q1a + posA);
        float vb = leaky(q2[j * 64 + lane + 32] + q1b + posB);
        s_v[rg][lane]      = va;
        s_v[rg][lane + 32] = vb;
        __syncwarp();
        float ha = mba, hb = mbb;
        #pragma unroll
        for (int c = 0; c < 64; ++c) {
            float vc = s_v[rg][c];
            ha = fmaf(s_mw[lane * 65 + c],        vc, ha);
            hb = fmaf(s_mw[(lane + 32) * 65 + c], vc, hb);
        }
        bestA = fmaxf(bestA, leaky(ha));
        bestB = fmaxf(bestB, leaky(hb));
        __syncwarp();
    }

    out[dir * (64 * N) + lane * N + row]        = bestA;
    out[dir * (64 * N) + (lane + 32) * N + row] = bestB;
}

// =====================================================================================
extern "C" void kernel_launch(void* const* d_in, const int* in_sizes, int n_in,
                              void* d_out, int out_size)
{
    const float* pc1   = (const float*)d_in[0];
    const float* pc2   = (const float*)d_in[1];
    const float* feat1 = (const float*)d_in[2];
    const float* feat2 = (const float*)d_in[3];
    const float* t11w  = (const float*)d_in[4];
    const float* t11b  = (const float*)d_in[5];
    const float* t22w  = (const float*)d_in[6];
    const float* t22b  = (const float*)d_in[7];
    const float* posw  = (const float*)d_in[8];
    const float* posb  = (const float*)d_in[9];
    const float* dw    = (const float*)d_in[10];
    const float* db    = (const float*)d_in[11];
    const float* mw    = (const float*)d_in[12];
    const float* mb    = (const float*)d_in[13];
    float* out = (float*)d_out;

    const int smP = 66816;
    cudaFuncSetAttribute(kp, cudaFuncAttributeMaxDynamicSharedMemorySize, smP);
    cudaFuncSetAttribute(kd, cudaFuncAttributeMaxDynamicSharedMemorySize, SM_BYTES);

    kp<<<dim3(N / 32, 4), 256, smP>>>(pc1, pc2, feat1, feat2,
                                      t11w, t11b, t22w, t22b, dw, db);
    kd<<<dim3(N / MT, 2), 128, SM_BYTES>>>();
    km<<<dim3(N / 8, 2), 256>>>(pc1, pc2, posw, posb, mw, mb, out);
}

// round 5
// speedup vs baseline: 1.7096x; 1.0998x over previous
#include <cuda_runtime.h>
#include <math.h>
#include <float.h>
#include <stdint.h>

#define N      8192
#define C0     64
#define KSEL   16
#define TCAND  24
#define MT     128
#define NT     64
#define NTILE  (N / NT)        // 128
#define KEXT   136             // 128 emb + 3 xyz + 1 + 4 zero pad
#define ASTR   140             // smem row stride (floats); 35x16B, odd -> LDSM conflict-free
#define CSTR   65

// ---------------- scratch ----------------
__device__ __align__(128) float g_f[4][N][C0];     // projected features [n][c]
__device__ __align__(128) float g_ge[4][N][KEXT];  // extended rows
__device__ int g_cand[2][N][TCAND];

__device__ __forceinline__ float leaky(float x) { return fmaxf(x, 0.1f * x); }

__device__ __forceinline__ uint32_t smem_u32(const void* p) {
    uint32_t a;
    asm("{ .reg .u64 t; cvta.to.shared.u64 t, %1; cvt.u32.u64 %0, t; }" : "=r"(a) : "l"(p));
    return a;
}
__device__ __forceinline__ void cp16(uint32_t dst, const void* src) {
    asm volatile("cp.async.cg.shared.global [%0], [%1], 16;" :: "r"(dst), "l"(src));
}
#define CP_COMMIT() asm volatile("cp.async.commit_group;" ::: "memory")
#define CP_WAIT0()  asm volatile("cp.async.wait_group 0;" ::: "memory")

__device__ __forceinline__ void ldsm4(uint32_t* r, uint32_t addr) {
    asm volatile("ldmatrix.sync.aligned.m8n8.x4.shared.b16 {%0,%1,%2,%3}, [%4];"
        : "=r"(r[0]), "=r"(r[1]), "=r"(r[2]), "=r"(r[3]) : "r"(addr));
}

__device__ __forceinline__ void mma_tf32(float* c, uint32_t a0, uint32_t a1,
                                         uint32_t a2, uint32_t a3,
                                         uint32_t b0, uint32_t b1) {
    asm volatile(
        "mma.sync.aligned.m16n8k8.row.col.f32.tf32.tf32.f32 "
        "{%0,%1,%2,%3}, {%4,%5,%6,%7}, {%8,%9}, {%0,%1,%2,%3};"
        : "+f"(c[0]), "+f"(c[1]), "+f"(c[2]), "+f"(c[3])
        : "r"(a0), "r"(a1), "r"(a2), "r"(a3), "r"(b0), "r"(b1));
}

// smem floats: A [128*140], B [2][64*140], C [128*65]
#define SM_A 0
#define SM_B (MT * ASTR)                    // 17920
#define SM_C (SM_B + 2 * NT * ASTR)         // 35840
#define SM_TOT_F (SM_C + MT * CSTR)         // 44160
#define SM_BYTES (SM_TOT_F * 4)             // 176640

// =====================================================================================
// Kernel P: projections + dist embedding + normalize + extended rows
// =====================================================================================
__global__ __launch_bounds__(256) void kp(
    const float* __restrict__ pc1, const float* __restrict__ pc2,
    const float* __restrict__ feat1, const float* __restrict__ feat2,
    const float* __restrict__ t11w, const float* __restrict__ t11b,
    const float* __restrict__ t22w, const float* __restrict__ t22b,
    const float* __restrict__ dw, const float* __restrict__ db)
{
    extern __shared__ float sm[];
    float* s_tw   = sm;
    float* s_dw   = sm + 4160;
    float* s_feat = sm + 4160 + 8320;
    float* s_f    = sm + 4160 + 8320 + 2112;
    float* s_ss   = s_f + 2080;

    const int combo = blockIdx.y;
    const float* feat = (combo == 0 || combo == 3) ? feat1 : feat2;
    const float* pc   = (combo == 0 || combo == 3) ? pc1   : pc2;
    const float* w    = (combo & 1) ? t22w : t11w;
    const float* b    = (combo & 1) ? t22b : t11b;
    const int side2   = combo & 1;

    const int tid = threadIdx.x;
    const int n0  = blockIdx.x * 32;

    for (int i = tid; i < 4096; i += 256) s_tw[(i >> 6) * 65 + (i & 63)] = w[i];
    for (int i = tid; i < 8192; i += 256) s_dw[(i >> 6) * 65 + (i & 63)] = dw[i];
    for (int i = tid; i < 64 * 32; i += 256) {
        int c = i >> 5, np = i & 31;
        s_feat[c * 33 + np] = feat[c * N + n0 + np];
    }
    if (tid < 32) s_ss[tid] = 0.f;
    __syncthreads();

    for (int it = 0; it < 8; ++it) {
        int i = tid + it * 256;
        int o = i & 63, n = i >> 6;
        float acc = __ldg(b + o);
        #pragma unroll
        for (int c = 0; c < 64; ++c)
            acc = fmaf(s_tw[o * 65 + c], s_feat[c * 33 + n], acc);
        s_f[n * 65 + o] = acc;
        g_f[combo][n0 + n][o] = acc;
    }
    __syncthreads();

    const int n = tid & 31, eg = tid >> 5;
    float gv[16];
    float ss = 0.f;
    #pragma unroll 2
    for (int t = 0; t < 16; ++t) {
        int e = eg * 16 + t;
        float acc = __ldg(db + e);
        #pragma unroll
        for (int c = 0; c < 64; ++c)
            acc = fmaf(s_dw[e * 65 + c], s_f[n * 65 + c], acc);
        gv[t] = acc;
        ss = fmaf(acc, acc, ss);
    }
    atomicAdd(&s_ss[n], ss);
    __syncthreads();
    const float scale = 1.f / (sqrtf(s_ss[n]) + 1e-8f);
    #pragma unroll
    for (int t = 0; t < 16; ++t)
        g_ge[combo][n0 + n][eg * 16 + t] = gv[t] * scale;

    if (tid < 32) {
        int nn = n0 + tid;
        float x0 = pc[0 * N + nn], x1 = pc[1 * N + nn], x2 = pc[2 * N + nn];
        float* row = &g_ge[combo][nn][128];
        if (side2) {
            row[0] = x0; row[1] = x1; row[2] = x2;
            row[3] = x0 * x0 + x1 * x1 + x2 * x2;
        } else {
            row[0] = 2.f * x0; row[1] = 2.f * x1; row[2] = 2.f * x2;
            row[3] = -1.f;
        }
        row[4] = 0.f; row[5] = 0.f; row[6] = 0.f; row[7] = 0.f;
    }
}

// =====================================================================================
// Kernel D: tf32 mma.sync score GEMM + streaming top-24.
// 256 threads (8 warps: 4 row-groups x 2 col-groups, warp tile 32x32).
// A resident smem, B double-buffered cp.async, fragments via ldmatrix.x4.
// =====================================================================================
__global__ __launch_bounds__(256, 1) void kd()
{
    extern __shared__ float sh[];
    const uint32_t sb = smem_u32(sh);
    float* s_c = sh + SM_C;

    const int tid  = threadIdx.x;
    const int wid  = tid >> 5, lane = tid & 31;
    const int dir  = blockIdx.y;
    const int row0 = blockIdx.x * MT;

    const int wr = wid & 3;            // row group: rows wr*32..wr*32+31
    const int wc = wid >> 2;           // col group: cols wc*32..wc*32+31

    const float* __restrict__ gA = &g_ge[dir * 2][0][0];
    const float* __restrict__ gB = &g_ge[dir * 2 + 1][0][0];

    // ---- A resident: 128 rows x 34 float4 ----
    #pragma unroll
    for (int it = 0; it < 17; ++it) {
        int i = tid + it * 256;               // 0..4351
        int r = i / 34, q = i % 34;
        cp16(sb + (SM_A + r * ASTR + q * 4) * 4,
             gA + (size_t)(row0 + r) * KEXT + q * 4);
    }
    // ---- B tile 0 prefetch: 64 rows x 34 float4 = 2176 ----
    #pragma unroll
    for (int it = 0; it < 9; ++it) {
        int i = tid + it * 256;
        if (i < 2176) {
            int r = i / 34, q = i % 34;
            cp16(sb + (SM_B + r * ASTR + q * 4) * 4,
                 gB + (size_t)r * KEXT + q * 4);
        }
    }
    CP_COMMIT();
    CP_WAIT0();
    __syncthreads();

    float ts[TCAND];
    int   ti[TCAND];
    #pragma unroll
    for (int q = 0; q < TCAND; ++q) { ts[q] = -FLT_MAX; ti[q] = 0; }

    // ---- ldmatrix per-thread base addresses ----
    // A fragment (rb in {0,1}): quad0 rows+0..7 k0-3; quad1 rows+8 k0-3; quad2 rows k4-7; quad3 rows+8 k4-7
    uint32_t a_base[2];
    {
        int r = wr * 32 + (lane & 7) + ((lane >> 3) & 1) * 8;
        int koff = (lane >> 4) * 4;
        a_base[0] = sb + (SM_A + r * ASTR + koff) * 4;
        a_base[1] = a_base[0] + 16 * ASTR * 4;
    }
    // B fragment (cbp in {0,1} covers cols pair): quad0 cols+0..7 k0-3; quad1 cols k4-7; quad2 cols+8 k0-3; quad3 cols+8 k4-7
    uint32_t b_off[2];
    {
        int cI = wc * 32 + (lane & 7) + (lane >> 4) * 8;
        int koff = ((lane >> 3) & 1) * 4;
        b_off[0] = (cI * ASTR + koff) * 4;
        b_off[1] = b_off[0] + 16 * ASTR * 4;
    }

    const int r0q = lane >> 2;            // fragment row within m16
    const int cq2 = (lane & 3) * 2;

    for (int t = 0; t < NTILE; ++t) {
        const uint32_t bbuf = sb + (SM_B + (t & 1) * (NT * ASTR)) * 4;

        // prefetch next tile into other buffer
        if (t + 1 < NTILE) {
            const uint32_t dstb = sb + (SM_B + ((t + 1) & 1) * (NT * ASTR)) * 4;
            const float* srcb = gB + (size_t)(t + 1) * NT * KEXT;
            #pragma unroll
            for (int it = 0; it < 9; ++it) {
                int i = tid + it * 256;
                if (i < 2176) {
                    int r = i / 34, q = i % 34;
                    cp16(dstb + (r * ASTR + q * 4) * 4, srcb + (size_t)r * KEXT + q * 4);
                }
            }
            CP_COMMIT();
        }

        // ---- MMA: warp tile 32x32, K=136 ----
        float c[2][4][4];
        #pragma unroll
        for (int rb = 0; rb < 2; ++rb)
            #pragma unroll
            for (int cb = 0; cb < 4; ++cb)
                #pragma unroll
                for (int q = 0; q < 4; ++q) c[rb][cb][q] = 0.f;

        #pragma unroll 1
        for (int kb = 0; kb < 17; ++kb) {
            const uint32_t kadd = kb * 32;
            uint32_t a[2][4], b[2][4];
            ldsm4(a[0], a_base[0] + kadd);
            ldsm4(a[1], a_base[1] + kadd);
            ldsm4(b[0], bbuf + b_off[0] + kadd);
            ldsm4(b[1], bbuf + b_off[1] + kadd);
            #pragma unroll
            for (int rb = 0; rb < 2; ++rb) {
                #pragma unroll
                for (int cbp = 0; cbp < 2; ++cbp) {
                    mma_tf32(c[rb][2 * cbp],     a[rb][0], a[rb][1], a[rb][2], a[rb][3],
                             b[cbp][0], b[cbp][1]);
                    mma_tf32(c[rb][2 * cbp + 1], a[rb][0], a[rb][1], a[rb][2], a[rb][3],
                             b[cbp][2], b[cbp][3]);
                }
            }
        }
        __syncthreads();

        // ---- stage C to smem ----
        #pragma unroll
        for (int rb = 0; rb < 2; ++rb) {
            const int rr = wr * 32 + rb * 16 + r0q;
            #pragma unroll
            for (int cb = 0; cb < 4; ++cb) {
                const int cc = wc * 32 + cb * 8 + cq2;
                s_c[rr * CSTR + cc]           = c[rb][cb][0];
                s_c[rr * CSTR + cc + 1]       = c[rb][cb][1];
                s_c[(rr + 8) * CSTR + cc]     = c[rb][cb][2];
                s_c[(rr + 8) * CSTR + cc + 1] = c[rb][cb][3];
            }
        }
        __syncthreads();

        // ---- per-row streaming top-24 (warps 0-3: thread = row) ----
        if (tid < 128) {
            const int jb0 = t * NT;
            const float* crow = s_c + tid * CSTR;
            #pragma unroll 1
            for (int cb = 0; cb < 8; ++cb) {
                float acc[8];
                unsigned m = 0;
                #pragma unroll
                for (int jj = 0; jj < 8; ++jj) {
                    acc[jj] = crow[cb * 8 + jj];
                    if (acc[jj] > ts[TCAND - 1]) m |= (1u << jj);
                }
                while (__any_sync(0xffffffffu, m != 0)) {
                    if (m) {
                        int jj = __ffs(m) - 1;
                        m &= m - 1;
                        float cs = acc[jj];
                        if (cs > ts[TCAND - 1]) {
                            int ci = jb0 + cb * 8 + jj;
                            #pragma unroll
                            for (int q = 0; q < TCAND; ++q) {
                                if (cs > ts[q]) {
                                    float tf = ts[q]; ts[q] = cs; cs = tf;
                                    int   tx = ti[q]; ti[q] = ci; ci = tx;
                                }
                            }
                        }
                    }
                }
            }
        }
        CP_WAIT0();
        __syncthreads();
    }

    if (tid < 128) {
        #pragma unroll
        for (int q = 0; q < TCAND; ++q)
            g_cand[dir][row0 + tid][q] = ti[q];
    }
}

// =====================================================================================
// Kernel M: exact fp32 rescore of 24 candidates -> top-16 -> gather+MLP+maxpool
// =====================================================================================
__device__ __forceinline__ unsigned long long makeKey(float s, int j)
{
    unsigned u = __float_as_uint(s);
    u = (u & 0x80000000u) ? ~u : (u | 0x80000000u);
    return ((unsigned long long)u << 32) | (unsigned)(~j);
}

__global__ __launch_bounds__(256) void km(
    const float* __restrict__ pc1, const float* __restrict__ pc2,
    const float* __restrict__ posw, const float* __restrict__ posb,
    const float* __restrict__ mw, const float* __restrict__ mb,
    float* __restrict__ out)
{
    __shared__ float s_mw[64 * 65];
    __shared__ float s_g1[8][KEXT];
    __shared__ int   s_sel[8][KSEL];
    __shared__ float s_v[8][65];

    const int tid  = threadIdx.x;
    const int lane = tid & 31;
    const int rg   = tid >> 5;
    const int dir  = blockIdx.y;
    const int row  = blockIdx.x * 8 + rg;

    const float* x1p = dir ? pc2 : pc1;
    const float* x2p = dir ? pc1 : pc2;
    const float* q1  = &g_f[dir * 2][0][0];
    const float* q2  = &g_f[dir * 2 + 1][0][0];
    const float* g1  = &g_ge[dir * 2][0][0];
    const float* g2  = &g_ge[dir * 2 + 1][0][0];

    for (int i = tid; i < 4096; i += 256)
        s_mw[(i >> 6) * 65 + (i & 63)] = mw[i];
    for (int i = tid; i < 8 * KEXT; i += 256)
        s_g1[i / KEXT][i % KEXT] =
            g1[(size_t)(blockIdx.x * 8 + i / KEXT) * KEXT + (i % KEXT)];
    __syncthreads();

    // exact rescore (lane < 24); pad zeros [132..135] contribute 0
    unsigned long long key = 0ULL;
    if (lane < TCAND) {
        int j = g_cand[dir][row][lane];
        const float4* g2r = (const float4*)(g2 + (size_t)j * KEXT);
        float s = 0.f;
        #pragma unroll 8
        for (int kqq = 0; kqq < 34; ++kqq) {
            float4 av = *(const float4*)&s_g1[rg][kqq * 4];
            float4 bv = __ldg(g2r + kqq);
            s = fmaf(av.x, bv.x, s); s = fmaf(av.y, bv.y, s);
            s = fmaf(av.z, bv.z, s); s = fmaf(av.w, bv.w, s);
        }
        key = makeKey(s, j);
    }

    #pragma unroll 1
    for (int r = 0; r < KSEL; ++r) {
        unsigned long long mx = key;
        #pragma unroll
        for (int off = 16; off; off >>= 1) {
            unsigned long long o = __shfl_xor_sync(0xffffffffu, mx, off);
            mx = (o > mx) ? o : mx;
        }
        if (lane == 0) s_sel[rg][r] = (int)(~(unsigned)mx);
        if (key == mx) key = 0ULL;
    }
    __syncwarp();

    const float x10 = x1p[row], x11 = x1p[N + row], x12 = x1p[2 * N + row];
    const float q1a = q1[row * 64 + lane];
    const float q1b = q1[row * 64 + lane + 32];
    const float pa0 = __ldg(posw + lane * 3 + 0), pa1 = __ldg(posw + lane * 3 + 1), pa2 = __ldg(posw + lane * 3 + 2);
    const float pb0 = __ldg(posw + (lane + 32) * 3 + 0), pb1 = __ldg(posw + (lane + 32) * 3 + 1), pb2 = __ldg(posw + (lane + 32) * 3 + 2);
    const float ba  = __ldg(posb + lane),      bb  = __ldg(posb + lane + 32);
    const float mba = __ldg(mb + lane),        mbb = __ldg(mb + lane + 32);

    float bestA = -FLT_MAX, bestB = -FLT_MAX;

    #pragma unroll 1
    for (int kk = 0; kk < KSEL; ++kk) {
        int j = s_sel[rg][kk];
        float d0 = x2p[j] - x10, d1 = x2p[N + j] - x11, d2 = x2p[2 * N + j] - x12;
        float posA = fmaf(pa2, d2, fmaf(pa1, d1, fmaf(pa0, d0, ba)));
        float posB = fmaf(pb2, d2, fmaf(pb1, d1, fmaf(pb0, d0, bb)));
        float va = leaky(q2[j * 64 + lane]      + q1a + posA);
        float vb = leaky(q2[j * 64 + lane + 32] + q1b + posB);
        s_v[rg][lane]      = va;
        s_v[rg][lane + 32] = vb;
        __syncwarp();
        float ha = mba, hb = mbb;
        #pragma unroll
        for (int c = 0; c < 64; ++c) {
            float vc = s_v[rg][c];
            ha = fmaf(s_mw[lane * 65 + c],        vc, ha);
            hb = fmaf(s_mw[(lane + 32) * 65 + c], vc, hb);
        }
        bestA = fmaxf(bestA, leaky(ha));
        bestB = fmaxf(bestB, leaky(hb));
        __syncwarp();
    }

    out[dir * (64 * N) + lane * N + row]        = bestA;
    out[dir * (64 * N) + (lane + 32) * N + row] = bestB;
}

// =====================================================================================
extern "C" void kernel_launch(void* const* d_in, const int* in_sizes, int n_in,
                              void* d_out, int out_size)
{
    const float* pc1   = (const float*)d_in[0];
    const float* pc2   = (const float*)d_in[1];
    const float* feat1 = (const float*)d_in[2];
    const float* feat2 = (const float*)d_in[3];
    const float* t11w  = (const float*)d_in[4];
    const float* t11b  = (const float*)d_in[5];
    const float* t22w  = (const float*)d_in[6];
    const float* t22b  = (const float*)d_in[7];
    const float* posw  = (const float*)d_in[8];
    const float* posb  = (const float*)d_in[9];
    const float* dw    = (const float*)d_in[10];
    const float* db    = (const float*)d_in[11];
    const float* mw    = (const float*)d_in[12];
    const float* mb    = (const float*)d_in[13];
    float* out = (float*)d_out;

    const int smP = 66816;
    cudaFuncSetAttribute(kp, cudaFuncAttributeMaxDynamicSharedMemorySize, smP);
    cudaFuncSetAttribute(kd, cudaFuncAttributeMaxDynamicSharedMemorySize, SM_BYTES);

    kp<<<dim3(N / 32, 4), 256, smP>>>(pc1, pc2, feat1, feat2,
                                      t11w, t11b, t22w, t22b, dw, db);
    kd<<<dim3(N / MT, 2), 256, SM_BYTES>>>();
    km<<<dim3(N / 8, 2), 256>>>(pc1, pc2, posw, posb, mw, mb, out);
}